// round 10
// baseline (speedup 1.0000x reference)
#include <cuda_runtime.h>
#include <cstdint>

#define S_LEN 4096
#define HID   512
#define NHEAD 8
#define HDIM  64
#define GK    512
#define GN    512

// Scratch (device globals — allocation-free per harness rules)
__device__ float g_q[S_LEN * HID];
__device__ float g_k[S_LEN * HID];
__device__ float g_v[S_LEN * HID];
__device__ float g_att[S_LEN * HID];

// ---------------------------------------------------------------------------
// Helpers
// ---------------------------------------------------------------------------
__device__ __forceinline__ uint32_t f2tf32(float f) {
    uint32_t u;
    asm("cvt.rna.tf32.f32 %0, %1;" : "=r"(u) : "f"(f));
    return u;
}

__device__ __forceinline__ void mma_tf32(float c[4], const uint32_t a[4],
                                         uint32_t b0, uint32_t b1) {
    asm volatile(
        "mma.sync.aligned.m16n8k8.row.col.f32.tf32.tf32.f32 "
        "{%0,%1,%2,%3}, {%4,%5,%6,%7}, {%8,%9}, {%0,%1,%2,%3};"
        : "+f"(c[0]), "+f"(c[1]), "+f"(c[2]), "+f"(c[3])
        : "r"(a[0]), "r"(a[1]), "r"(a[2]), "r"(a[3]), "r"(b0), "r"(b1));
}

__device__ __forceinline__ uint32_t smem_u32(const void* p) {
    return (uint32_t)__cvta_generic_to_shared(p);
}

__device__ __forceinline__ void cp16(uint32_t dst, const float* src) {
    asm volatile("cp.async.cg.shared.global [%0], [%1], 16;" :: "r"(dst), "l"(src));
}
#define CP_COMMIT() asm volatile("cp.async.commit_group;")
#define CP_WAIT0()  asm volatile("cp.async.wait_group 0;")

// ---------------------------------------------------------------------------
// C[4096,512] = A[4096,512] * B[512,512]^T  (NT, tf32 mma, fp32 accum)
// CTA 128x128, BK=32, 256 thr (8 warps 2x4), warp tile 64x32.
// cp.async double-buffered; raw fp32 in smem (stride 36 == 4 mod 32,
// frag LDS conflict-free); cvt.rna at frag load (rounding bias-free).
// gridDim.z selects (B,C) so QKV is one launch.
// ---------------------------------------------------------------------------
#define GA_BUF (128 * 36)
#define GB_BUF (128 * 36)
#define GEMM_SMEM ((2 * GA_BUF + 2 * GB_BUF) * 4)   // 73728 B

__global__ __launch_bounds__(256) void gemm_tf32(const float* __restrict__ A,
                                                 const float* __restrict__ B0,
                                                 const float* __restrict__ B1,
                                                 const float* __restrict__ B2,
                                                 float* __restrict__ C0,
                                                 float* __restrict__ C1,
                                                 float* __restrict__ C2) {
    extern __shared__ float gsm[];
    float* Asm = gsm;                 // [2][128][36]
    float* Bsm = gsm + 2 * GA_BUF;    // [2][128][36]
    const uint32_t sA = smem_u32(Asm);
    const uint32_t sB = smem_u32(Bsm);

    const float* B = (blockIdx.z == 0) ? B0 : (blockIdx.z == 1) ? B1 : B2;
    float*       C = (blockIdx.z == 0) ? C0 : (blockIdx.z == 1) ? C1 : C2;

    const int tid = threadIdx.x;
    const int lane = tid & 31;
    const int warp = tid >> 5;
    const int g = lane >> 2;
    const int c = lane & 3;
    const int warp_m = warp & 1;      // 2 warps in m (64 rows each)
    const int warp_n = warp >> 1;     // 4 warps in n (32 cols each)
    const int mb = blockIdx.y * 128;
    const int nb = blockIdx.x * 128;

    auto stage = [&](int kb, int buf) {
        const int ab = buf * GA_BUF, bb = buf * GB_BUF;
#pragma unroll
        for (int i = 0; i < 4; i++) {
            int fid = tid + i * 256;
            int r = fid >> 3, c4 = fid & 7;
            cp16(sA + (ab + r * 36 + c4 * 4) * 4, A + (mb + r) * GK + kb + c4 * 4);
            cp16(sB + (bb + r * 36 + c4 * 4) * 4, B + (nb + r) * GK + kb + c4 * 4);
        }
        CP_COMMIT();
    };

    float acc[4][4][4];
#pragma unroll
    for (int mf = 0; mf < 4; mf++)
#pragma unroll
        for (int nf = 0; nf < 4; nf++)
#pragma unroll
            for (int r = 0; r < 4; r++) acc[mf][nf][r] = 0.f;

    stage(0, 0);

    for (int ib = 0; ib < GK / 32; ib++) {
        CP_WAIT0();
        __syncthreads();
        if (ib + 1 < GK / 32) stage((ib + 1) * 32, (ib + 1) & 1);

        const float* Ab = Asm + (ib & 1) * GA_BUF;
        const float* Bb = Bsm + (ib & 1) * GB_BUF;
#pragma unroll
        for (int ks = 0; ks < 4; ks++) {
            const int kk = ks * 8;
            uint32_t a[4][4];
#pragma unroll
            for (int mf = 0; mf < 4; mf++) {
                int rowb = warp_m * 64 + mf * 16 + g;
                a[mf][0] = f2tf32(Ab[rowb * 36 + kk + c]);
                a[mf][1] = f2tf32(Ab[(rowb + 8) * 36 + kk + c]);
                a[mf][2] = f2tf32(Ab[rowb * 36 + kk + c + 4]);
                a[mf][3] = f2tf32(Ab[(rowb + 8) * 36 + kk + c + 4]);
            }
            uint32_t b[4][2];
#pragma unroll
            for (int nf = 0; nf < 4; nf++) {
                int colb = warp_n * 32 + nf * 8 + g;
                b[nf][0] = f2tf32(Bb[colb * 36 + kk + c]);
                b[nf][1] = f2tf32(Bb[colb * 36 + kk + c + 4]);
            }
#pragma unroll
            for (int mf = 0; mf < 4; mf++)
#pragma unroll
                for (int nf = 0; nf < 4; nf++)
                    mma_tf32(acc[mf][nf], a[mf], b[nf][0], b[nf][1]);
        }
    }

#pragma unroll
    for (int mf = 0; mf < 4; mf++) {
        int row = mb + warp_m * 64 + mf * 16 + g;
#pragma unroll
        for (int nf = 0; nf < 4; nf++) {
            int col = nb + warp_n * 32 + nf * 8 + 2 * c;
            *reinterpret_cast<float2*>(&C[row * GN + col]) =
                make_float2(acc[mf][nf][0], acc[mf][nf][1]);
            *reinterpret_cast<float2*>(&C[(row + 8) * GN + col]) =
                make_float2(acc[mf][nf][2], acc[mf][nf][3]);
        }
    }
}

// ---------------------------------------------------------------------------
// RoPE on Q and K, positions s >= num_registers.
// ---------------------------------------------------------------------------
__global__ void rope_kernel(float* __restrict__ q, float* __restrict__ k,
                            const float* __restrict__ cosb,
                            const float* __restrict__ sinb,
                            const int* __restrict__ nregp) {
    const int nreg = *nregp;
    int idx = blockIdx.x * blockDim.x + threadIdx.x;
    if (idx >= S_LEN * NHEAD * 32) return;
    int j = idx & 31;
    int h = (idx >> 5) & 7;
    int s = idx >> 8;
    if (s < nreg) return;
    int p = s - nreg;
    float c  = cosb[p * HDIM + j];
    float sn = sinb[p * HDIM + j];
    int base = s * HID + h * HDIM + j;
    float q1 = q[base], q2 = q[base + 32];
    q[base]      = q1 * c - q2 * sn;
    q[base + 32] = q2 * c + q1 * sn;
    float k1 = k[base], k2 = k[base + 32];
    k[base]      = k1 * c - k2 * sn;
    k[base + 32] = k2 * c + k1 * sn;
}

// ---------------------------------------------------------------------------
// Flash attention, causal, tf32 mma, cp.async double-buffered KV.
// 128-query tile, 256 thr (8 warps x 16 rows), 64-key tiles.
// K raw fp32 stride 68 (==4 mod 32), V stride 72 (==8 mod 32), P (tf32)
// in its own 128x68 buffer -> one __syncthreads per tile. Warps whose
// rows are entirely masked on diagonal tiles skip compute.
// 2 CTAs/SM (106.5 KB smem each).
// ---------------------------------------------------------------------------
#define KSTRIDE 68
#define VSTRIDE 72
#define KBUF (64 * KSTRIDE)          // 4352 words
#define VBUF (64 * VSTRIDE)          // 4608 words
#define PBUF (128 * KSTRIDE)         // 8704 words
#define AT_SMEM ((2 * KBUF + 2 * VBUF + PBUF) * 4)   // 106496 B

__global__ __launch_bounds__(256, 2) void attn_mma(const float* __restrict__ Q,
                                                   const float* __restrict__ Kg,
                                                   const float* __restrict__ Vg,
                                                   float* __restrict__ O) {
    extern __shared__ float sm[];
    float* Ksm = sm;                        // [2][64][68]
    float* Vsm = sm + 2 * KBUF;             // [2][64][72]
    uint32_t* Psm = reinterpret_cast<uint32_t*>(sm + 2 * KBUF + 2 * VBUF); // [128][68]
    const uint32_t sK = smem_u32(Ksm);
    const uint32_t sV = smem_u32(Vsm);

    const int tid  = threadIdx.x;
    const int lane = tid & 31;
    const int w    = tid >> 5;
    const int g    = lane >> 2;
    const int c    = lane & 3;
    const int head = blockIdx.x & 7;
    const int qt   = 31 - (blockIdx.x >> 3);   // descending for LPT packing
    const int qbase = qt * 128;
    const int hoff  = head * HDIM;
    const int ntiles = 2 * qt + 2;

    auto stage = [&](int t, int buf) {
        const int kb0 = t * 64;
        const int kb = buf * KBUF, vb = buf * VBUF;
#pragma unroll
        for (int i = 0; i < 4; i++) {
            int fid = tid + i * 256;
            int r = fid >> 4, c4 = fid & 15;
            cp16(sK + (kb + r * KSTRIDE + c4 * 4) * 4,
                 Kg + (kb0 + r) * HID + hoff + c4 * 4);
            cp16(sV + (vb + r * VSTRIDE + c4 * 4) * 4,
                 Vg + (kb0 + r) * HID + hoff + c4 * 4);
        }
        CP_COMMIT();
    };

    stage(0, 0);

    // Q fragments in registers, pre-scaled by 1/sqrt(64)
    uint32_t qa[8][4];
    {
        const float scale = 0.125f;
        const float* q0 = Q + (qbase + w * 16 + g) * HID + hoff;
        const float* q1 = q0 + 8 * HID;
#pragma unroll
        for (int ks = 0; ks < 8; ks++) {
            qa[ks][0] = f2tf32(scale * __ldg(q0 + ks * 8 + c));
            qa[ks][1] = f2tf32(scale * __ldg(q1 + ks * 8 + c));
            qa[ks][2] = f2tf32(scale * __ldg(q0 + ks * 8 + c + 4));
            qa[ks][3] = f2tf32(scale * __ldg(q1 + ks * 8 + c + 4));
        }
    }

    float o[8][4];
#pragma unroll
    for (int nf = 0; nf < 8; nf++)
#pragma unroll
        for (int r = 0; r < 4; r++) o[nf][r] = 0.f;
    float m0 = -1e30f, m1 = -1e30f, l0 = 0.f, l1 = 0.f;

    const int prow0 = (w * 16 + g) * KSTRIDE;
    const int prow1 = (w * 16 + g + 8) * KSTRIDE;

    for (int t = 0; t < ntiles; t++) {
        const int kb0 = t * 64;
        CP_WAIT0();
        __syncthreads();   // tile t visible; all warps done with prior buf reads
        if (t + 1 < ntiles) stage(t + 1, (t + 1) & 1);

        const float* Kf = Ksm + (t & 1) * KBUF;
        const float* Vf = Vsm + (t & 1) * VBUF;

        // warp fully below this key tile? (all keys masked -> contribution 0)
        const bool active = (kb0 <= qbase + w * 16 + 15);
        if (active) {
            // S = Q K^T
            float s[8][4];
#pragma unroll
            for (int nf = 0; nf < 8; nf++)
#pragma unroll
                for (int r = 0; r < 4; r++) s[nf][r] = 0.f;
#pragma unroll
            for (int ks = 0; ks < 8; ks++) {
                const int kk = ks * 8;
#pragma unroll
                for (int nf = 0; nf < 8; nf++) {
                    uint32_t b0 = f2tf32(Kf[(nf * 8 + g) * KSTRIDE + kk + c]);
                    uint32_t b1 = f2tf32(Kf[(nf * 8 + g) * KSTRIDE + kk + c + 4]);
                    mma_tf32(s[nf], qa[ks], b0, b1);
                }
            }

            // causal mask (only when this tile straddles the warp's rows)
            if (kb0 + 63 > qbase + w * 16) {
                int row0 = qbase + w * 16 + g, row1 = row0 + 8;
#pragma unroll
                for (int nf = 0; nf < 8; nf++) {
                    int key = kb0 + nf * 8 + 2 * c;
                    if (key     > row0) s[nf][0] = -1e30f;
                    if (key + 1 > row0) s[nf][1] = -1e30f;
                    if (key     > row1) s[nf][2] = -1e30f;
                    if (key + 1 > row1) s[nf][3] = -1e30f;
                }
            }

            // online softmax (rows r0: regs 0,1 / r1: regs 2,3)
            float mx0 = -1e30f, mx1 = -1e30f;
#pragma unroll
            for (int nf = 0; nf < 8; nf++) {
                mx0 = fmaxf(mx0, fmaxf(s[nf][0], s[nf][1]));
                mx1 = fmaxf(mx1, fmaxf(s[nf][2], s[nf][3]));
            }
            mx0 = fmaxf(mx0, __shfl_xor_sync(0xffffffffu, mx0, 1));
            mx0 = fmaxf(mx0, __shfl_xor_sync(0xffffffffu, mx0, 2));
            mx1 = fmaxf(mx1, __shfl_xor_sync(0xffffffffu, mx1, 1));
            mx1 = fmaxf(mx1, __shfl_xor_sync(0xffffffffu, mx1, 2));
            float mn0 = fmaxf(m0, mx0), mn1 = fmaxf(m1, mx1);
            float al0 = __expf(m0 - mn0), al1 = __expf(m1 - mn1);
            float sum0 = 0.f, sum1 = 0.f;
#pragma unroll
            for (int nf = 0; nf < 8; nf++) {
                s[nf][0] = __expf(s[nf][0] - mn0);
                s[nf][1] = __expf(s[nf][1] - mn0);
                sum0 += s[nf][0] + s[nf][1];
                s[nf][2] = __expf(s[nf][2] - mn1);
                s[nf][3] = __expf(s[nf][3] - mn1);
                sum1 += s[nf][2] + s[nf][3];
            }
            sum0 += __shfl_xor_sync(0xffffffffu, sum0, 1);
            sum0 += __shfl_xor_sync(0xffffffffu, sum0, 2);
            sum1 += __shfl_xor_sync(0xffffffffu, sum1, 1);
            sum1 += __shfl_xor_sync(0xffffffffu, sum1, 2);
            l0 = l0 * al0 + sum0;  m0 = mn0;
            l1 = l1 * al1 + sum1;  m1 = mn1;
#pragma unroll
            for (int nf = 0; nf < 8; nf++) {
                o[nf][0] *= al0;  o[nf][1] *= al0;
                o[nf][2] *= al1;  o[nf][3] *= al1;
            }

            // stash P as tf32 (rows warp-private -> __syncwarp suffices)
#pragma unroll
            for (int nf = 0; nf < 8; nf++) {
                *reinterpret_cast<uint2*>(&Psm[prow0 + nf * 8 + 2 * c]) =
                    make_uint2(f2tf32(s[nf][0]), f2tf32(s[nf][1]));
                *reinterpret_cast<uint2*>(&Psm[prow1 + nf * 8 + 2 * c]) =
                    make_uint2(f2tf32(s[nf][2]), f2tf32(s[nf][3]));
            }
            __syncwarp();

            // O += P V
#pragma unroll
            for (int ks = 0; ks < 8; ks++) {
                const int kk = ks * 8;
                uint32_t a[4];
                a[0] = Psm[prow0 + kk + c];
                a[1] = Psm[prow1 + kk + c];
                a[2] = Psm[prow0 + kk + c + 4];
                a[3] = Psm[prow1 + kk + c + 4];
#pragma unroll
                for (int nf = 0; nf < 8; nf++) {
                    uint32_t b0 = f2tf32(Vf[(kk + c) * VSTRIDE + nf * 8 + g]);
                    uint32_t b1 = f2tf32(Vf[(kk + c + 4) * VSTRIDE + nf * 8 + g]);
                    mma_tf32(o[nf], a, b0, b1);
                }
            }
        }
    }

    // epilogue
    float inv0 = 1.0f / l0, inv1 = 1.0f / l1;
    int row = qbase + w * 16 + g;
#pragma unroll
    for (int nf = 0; nf < 8; nf++) {
        int col = hoff + nf * 8 + 2 * c;
        *reinterpret_cast<float2*>(&O[row * HID + col]) =
            make_float2(o[nf][0] * inv0, o[nf][1] * inv0);
        *reinterpret_cast<float2*>(&O[(row + 8) * HID + col]) =
            make_float2(o[nf][2] * inv1, o[nf][3] * inv1);
    }
}

// ---------------------------------------------------------------------------
// Host launcher (graph-capturable: kernel launches only)
// Inputs: hidden, Wq, Wk, Wv, Wo, cos, sin, num_registers
// ---------------------------------------------------------------------------
extern "C" void kernel_launch(void* const* d_in, const int* in_sizes, int n_in,
                              void* d_out, int out_size) {
    const float* hs   = (const float*)d_in[0];
    const float* Wq   = (const float*)d_in[1];
    const float* Wk   = (const float*)d_in[2];
    const float* Wv   = (const float*)d_in[3];
    const float* Wo   = (const float*)d_in[4];
    const float* cosb = (const float*)d_in[5];
    const float* sinb = (const float*)d_in[6];
    const int*   nreg = (const int*)d_in[7];
    float* out = (float*)d_out;

    float *qp, *kp, *vp, *ap;
    cudaGetSymbolAddress((void**)&qp, g_q);
    cudaGetSymbolAddress((void**)&kp, g_k);
    cudaGetSymbolAddress((void**)&vp, g_v);
    cudaGetSymbolAddress((void**)&ap, g_att);

    cudaFuncSetAttribute(gemm_tf32, cudaFuncAttributeMaxDynamicSharedMemorySize, GEMM_SMEM);
    cudaFuncSetAttribute(attn_mma,  cudaFuncAttributeMaxDynamicSharedMemorySize, AT_SMEM);

    // fused QKV projections (gridDim.z selects weight/output)
    dim3 qkv_grid(GN / 128, S_LEN / 128, 3);
    gemm_tf32<<<qkv_grid, 256, GEMM_SMEM>>>(hs, Wq, Wk, Wv, qp, kp, vp);

    rope_kernel<<<(S_LEN * NHEAD * 32 + 255) / 256, 256>>>(qp, kp, cosb, sinb, nreg);

    attn_mma<<<256, 256, AT_SMEM>>>(qp, kp, vp, ap);

    dim3 o_grid(GN / 128, S_LEN / 128, 1);
    gemm_tf32<<<o_grid, 256, GEMM_SMEM>>>(ap, Wo, Wo, Wo, out, out, out);
}

// round 11
// speedup vs baseline: 1.8721x; 1.8721x over previous
#include <cuda_runtime.h>
#include <cstdint>

#define S_LEN 4096
#define HID   512
#define NHEAD 8
#define HDIM  64
#define GK    512
#define GN    512

// Scratch (device globals — allocation-free per harness rules)
__device__ float g_q[S_LEN * HID];
__device__ float g_k[S_LEN * HID];
__device__ float g_v[S_LEN * HID];
__device__ float g_att[S_LEN * HID];

// ---------------------------------------------------------------------------
// Helpers
// ---------------------------------------------------------------------------
__device__ __forceinline__ uint32_t f2tf32(float f) {
    uint32_t u;
    asm("cvt.rna.tf32.f32 %0, %1;" : "=r"(u) : "f"(f));
    return u;
}

__device__ __forceinline__ void mma_tf32(float c[4], const uint32_t a[4],
                                         uint32_t b0, uint32_t b1) {
    asm volatile(
        "mma.sync.aligned.m16n8k8.row.col.f32.tf32.tf32.f32 "
        "{%0,%1,%2,%3}, {%4,%5,%6,%7}, {%8,%9}, {%0,%1,%2,%3};"
        : "+f"(c[0]), "+f"(c[1]), "+f"(c[2]), "+f"(c[3])
        : "r"(a[0]), "r"(a[1]), "r"(a[2]), "r"(a[3]), "r"(b0), "r"(b1));
}

__device__ __forceinline__ uint32_t smem_u32(const void* p) {
    return (uint32_t)__cvta_generic_to_shared(p);
}

__device__ __forceinline__ void cp16(uint32_t dst, const float* src) {
    asm volatile("cp.async.cg.shared.global [%0], [%1], 16;" :: "r"(dst), "l"(src));
}
#define CP_COMMIT() asm volatile("cp.async.commit_group;")
#define CP_WAIT0()  asm volatile("cp.async.wait_group 0;")

// ---------------------------------------------------------------------------
// C[4096,512] = A[4096,512] * B[512,512]^T  (NT, tf32 mma, fp32 accum)
// CTA 128x64, BK=32, 256 thr (8 warps 4x2), warp tile 32x32.
// cp.async double-buffered; raw fp32 in smem (stride 36 == 4 mod 32,
// frag LDS conflict-free); cvt.rna at frag load.
// __launch_bounds__(256,3): reg cap 85 (uses ~80) -> 3 CTAs/SM, no spill.
// gridDim.z selects (B,C) so QKV is one launch.
// ---------------------------------------------------------------------------
#define GA_BUF (128 * 36)
#define GB_BUF (64 * 36)
#define GEMM_SMEM ((2 * GA_BUF + 2 * GB_BUF) * 4)   // 55296 B

__global__ __launch_bounds__(256, 3) void gemm_tf32(const float* __restrict__ A,
                                                    const float* __restrict__ B0,
                                                    const float* __restrict__ B1,
                                                    const float* __restrict__ B2,
                                                    float* __restrict__ C0,
                                                    float* __restrict__ C1,
                                                    float* __restrict__ C2) {
    extern __shared__ float gsm[];
    float* Asm = gsm;                 // [2][128][36]
    float* Bsm = gsm + 2 * GA_BUF;    // [2][64][36]
    const uint32_t sA = smem_u32(Asm);
    const uint32_t sB = smem_u32(Bsm);

    const float* B = (blockIdx.z == 0) ? B0 : (blockIdx.z == 1) ? B1 : B2;
    float*       C = (blockIdx.z == 0) ? C0 : (blockIdx.z == 1) ? C1 : C2;

    const int tid = threadIdx.x;
    const int lane = tid & 31;
    const int warp = tid >> 5;
    const int g = lane >> 2;
    const int c = lane & 3;
    const int warp_m = warp & 3;      // 4 warps in m
    const int warp_n = warp >> 2;     // 2 warps in n
    const int mb = blockIdx.y * 128;
    const int nb = blockIdx.x * 64;

    auto stage = [&](int kb, int buf) {
        const int ab = buf * GA_BUF, bb = buf * GB_BUF;
#pragma unroll
        for (int i = 0; i < 4; i++) {
            int fid = tid + i * 256;
            int r = fid >> 3, c4 = fid & 7;
            cp16(sA + (ab + r * 36 + c4 * 4) * 4, A + (mb + r) * GK + kb + c4 * 4);
        }
#pragma unroll
        for (int i = 0; i < 2; i++) {
            int fid = tid + i * 256;
            int r = fid >> 3, c4 = fid & 7;
            cp16(sB + (bb + r * 36 + c4 * 4) * 4, B + (nb + r) * GK + kb + c4 * 4);
        }
        CP_COMMIT();
    };

    float acc[2][4][4];
#pragma unroll
    for (int mf = 0; mf < 2; mf++)
#pragma unroll
        for (int nf = 0; nf < 4; nf++)
#pragma unroll
            for (int r = 0; r < 4; r++) acc[mf][nf][r] = 0.f;

    stage(0, 0);

    for (int ib = 0; ib < GK / 32; ib++) {
        CP_WAIT0();
        __syncthreads();   // tile ib visible; all warps done with buf[(ib+1)&1]
        if (ib + 1 < GK / 32) stage((ib + 1) * 32, (ib + 1) & 1);

        const float* Ab = Asm + (ib & 1) * GA_BUF;
        const float* Bb = Bsm + (ib & 1) * GB_BUF;
#pragma unroll
        for (int ks = 0; ks < 4; ks++) {
            const int kk = ks * 8;
            uint32_t a[2][4];
#pragma unroll
            for (int mf = 0; mf < 2; mf++) {
                int rowb = warp_m * 32 + mf * 16 + g;
                a[mf][0] = f2tf32(Ab[rowb * 36 + kk + c]);
                a[mf][1] = f2tf32(Ab[(rowb + 8) * 36 + kk + c]);
                a[mf][2] = f2tf32(Ab[rowb * 36 + kk + c + 4]);
                a[mf][3] = f2tf32(Ab[(rowb + 8) * 36 + kk + c + 4]);
            }
            uint32_t b[4][2];
#pragma unroll
            for (int nf = 0; nf < 4; nf++) {
                int colb = warp_n * 32 + nf * 8 + g;
                b[nf][0] = f2tf32(Bb[colb * 36 + kk + c]);
                b[nf][1] = f2tf32(Bb[colb * 36 + kk + c + 4]);
            }
#pragma unroll
            for (int mf = 0; mf < 2; mf++)
#pragma unroll
                for (int nf = 0; nf < 4; nf++)
                    mma_tf32(acc[mf][nf], a[mf], b[nf][0], b[nf][1]);
        }
    }

#pragma unroll
    for (int mf = 0; mf < 2; mf++) {
        int row = mb + warp_m * 32 + mf * 16 + g;
#pragma unroll
        for (int nf = 0; nf < 4; nf++) {
            int col = nb + warp_n * 32 + nf * 8 + 2 * c;
            *reinterpret_cast<float2*>(&C[row * GN + col]) =
                make_float2(acc[mf][nf][0], acc[mf][nf][1]);
            *reinterpret_cast<float2*>(&C[(row + 8) * GN + col]) =
                make_float2(acc[mf][nf][2], acc[mf][nf][3]);
        }
    }
}

// ---------------------------------------------------------------------------
// RoPE on Q and K, positions s >= num_registers.
// ---------------------------------------------------------------------------
__global__ void rope_kernel(float* __restrict__ q, float* __restrict__ k,
                            const float* __restrict__ cosb,
                            const float* __restrict__ sinb,
                            const int* __restrict__ nregp) {
    const int nreg = *nregp;
    int idx = blockIdx.x * blockDim.x + threadIdx.x;
    if (idx >= S_LEN * NHEAD * 32) return;
    int j = idx & 31;
    int h = (idx >> 5) & 7;
    int s = idx >> 8;
    if (s < nreg) return;
    int p = s - nreg;
    float c  = cosb[p * HDIM + j];
    float sn = sinb[p * HDIM + j];
    int base = s * HID + h * HDIM + j;
    float q1 = q[base], q2 = q[base + 32];
    q[base]      = q1 * c - q2 * sn;
    q[base + 32] = q2 * c + q1 * sn;
    float k1 = k[base], k2 = k[base + 32];
    k[base]      = k1 * c - k2 * sn;
    k[base + 32] = k2 * c + k1 * sn;
}

// ---------------------------------------------------------------------------
// Flash attention, causal, tf32 mma, cp.async double-buffered KV.
// 64-query tile, 128 thr (4 warps x 16 rows) -- reg cap 170 at 3 CTAs/SM,
// no spills (R10 showed 256thr/2CTA spills). K stride 68 (==4 mod 32),
// V stride 72 (==8 mod 32), P (tf32) aliases the current K buffer after
// the S phase. 3 CTAs/SM (71.7 KB smem each).
// ---------------------------------------------------------------------------
#define KSTRIDE 68
#define VSTRIDE 72
#define KBUF (64 * KSTRIDE)          // 4352 words
#define VBUF (64 * VSTRIDE)          // 4608 words
#define AT_SMEM ((2 * KBUF + 2 * VBUF) * 4)   // 71680 B

__global__ __launch_bounds__(128, 3) void attn_mma(const float* __restrict__ Q,
                                                   const float* __restrict__ Kg,
                                                   const float* __restrict__ Vg,
                                                   float* __restrict__ O) {
    extern __shared__ float sm[];
    float* Ksm = sm;                  // [2][64][68]
    float* Vsm = sm + 2 * KBUF;       // [2][64][72]
    const uint32_t sK = smem_u32(Ksm);
    const uint32_t sV = smem_u32(Vsm);

    const int tid  = threadIdx.x;
    const int lane = tid & 31;
    const int w    = tid >> 5;
    const int g    = lane >> 2;
    const int c    = lane & 3;
    const int head = blockIdx.x & 7;
    const int qt   = 63 - (blockIdx.x >> 3);   // descending for LPT packing
    const int qbase = qt * 64;
    const int hoff  = head * HDIM;

    auto stage = [&](int t, int buf) {
        const int kb0 = t * 64;
        const int kb = buf * KBUF, vb = buf * VBUF;
#pragma unroll
        for (int i = 0; i < 8; i++) {
            int fid = tid + i * 128;
            int r = fid >> 4, c4 = fid & 15;
            cp16(sK + (kb + r * KSTRIDE + c4 * 4) * 4,
                 Kg + (kb0 + r) * HID + hoff + c4 * 4);
            cp16(sV + (vb + r * VSTRIDE + c4 * 4) * 4,
                 Vg + (kb0 + r) * HID + hoff + c4 * 4);
        }
        CP_COMMIT();
    };

    stage(0, 0);

    // Q fragments in registers, pre-scaled by 1/sqrt(64)
    uint32_t qa[8][4];
    {
        const float scale = 0.125f;
        const float* q0 = Q + (qbase + w * 16 + g) * HID + hoff;
        const float* q1 = q0 + 8 * HID;
#pragma unroll
        for (int ks = 0; ks < 8; ks++) {
            qa[ks][0] = f2tf32(scale * __ldg(q0 + ks * 8 + c));
            qa[ks][1] = f2tf32(scale * __ldg(q1 + ks * 8 + c));
            qa[ks][2] = f2tf32(scale * __ldg(q0 + ks * 8 + c + 4));
            qa[ks][3] = f2tf32(scale * __ldg(q1 + ks * 8 + c + 4));
        }
    }

    float o[8][4];
#pragma unroll
    for (int nf = 0; nf < 8; nf++)
#pragma unroll
        for (int r = 0; r < 4; r++) o[nf][r] = 0.f;
    float m0 = -1e30f, m1 = -1e30f, l0 = 0.f, l1 = 0.f;

    const int prow0 = (w * 16 + g) * KSTRIDE;
    const int prow1 = (w * 16 + g + 8) * KSTRIDE;

    for (int t = 0; t <= qt; t++) {
        CP_WAIT0();
        __syncthreads();   // tile t visible; all warps done with prior P/V reads
        if (t < qt) stage(t + 1, (t + 1) & 1);

        const float* Kf = Ksm + (t & 1) * KBUF;
        const float* Vf = Vsm + (t & 1) * VBUF;

        // S = Q K^T
        float s[8][4];
#pragma unroll
        for (int nf = 0; nf < 8; nf++)
#pragma unroll
            for (int r = 0; r < 4; r++) s[nf][r] = 0.f;
#pragma unroll
        for (int ks = 0; ks < 8; ks++) {
            const int kk = ks * 8;
#pragma unroll
            for (int nf = 0; nf < 8; nf++) {
                uint32_t b0 = f2tf32(Kf[(nf * 8 + g) * KSTRIDE + kk + c]);
                uint32_t b1 = f2tf32(Kf[(nf * 8 + g) * KSTRIDE + kk + c + 4]);
                mma_tf32(s[nf], qa[ks], b0, b1);
            }
        }

        if (t == qt) {   // diagonal tile mask (local coords)
            int row0 = w * 16 + g, row1 = row0 + 8;
#pragma unroll
            for (int nf = 0; nf < 8; nf++) {
                int col = nf * 8 + 2 * c;
                if (col     > row0) s[nf][0] = -1e30f;
                if (col + 1 > row0) s[nf][1] = -1e30f;
                if (col     > row1) s[nf][2] = -1e30f;
                if (col + 1 > row1) s[nf][3] = -1e30f;
            }
        }

        // online softmax (rows r0: regs 0,1 / r1: regs 2,3)
        float mx0 = -1e30f, mx1 = -1e30f;
#pragma unroll
        for (int nf = 0; nf < 8; nf++) {
            mx0 = fmaxf(mx0, fmaxf(s[nf][0], s[nf][1]));
            mx1 = fmaxf(mx1, fmaxf(s[nf][2], s[nf][3]));
        }
        mx0 = fmaxf(mx0, __shfl_xor_sync(0xffffffffu, mx0, 1));
        mx0 = fmaxf(mx0, __shfl_xor_sync(0xffffffffu, mx0, 2));
        mx1 = fmaxf(mx1, __shfl_xor_sync(0xffffffffu, mx1, 1));
        mx1 = fmaxf(mx1, __shfl_xor_sync(0xffffffffu, mx1, 2));
        float mn0 = fmaxf(m0, mx0), mn1 = fmaxf(m1, mx1);
        float al0 = __expf(m0 - mn0), al1 = __expf(m1 - mn1);
        float sum0 = 0.f, sum1 = 0.f;
#pragma unroll
        for (int nf = 0; nf < 8; nf++) {
            s[nf][0] = __expf(s[nf][0] - mn0);
            s[nf][1] = __expf(s[nf][1] - mn0);
            sum0 += s[nf][0] + s[nf][1];
            s[nf][2] = __expf(s[nf][2] - mn1);
            s[nf][3] = __expf(s[nf][3] - mn1);
            sum1 += s[nf][2] + s[nf][3];
        }
        sum0 += __shfl_xor_sync(0xffffffffu, sum0, 1);
        sum0 += __shfl_xor_sync(0xffffffffu, sum0, 2);
        sum1 += __shfl_xor_sync(0xffffffffu, sum1, 1);
        sum1 += __shfl_xor_sync(0xffffffffu, sum1, 2);
        l0 = l0 * al0 + sum0;  m0 = mn0;
        l1 = l1 * al1 + sum1;  m1 = mn1;
#pragma unroll
        for (int nf = 0; nf < 8; nf++) {
            o[nf][0] *= al0;  o[nf][1] *= al0;
            o[nf][2] *= al1;  o[nf][3] *= al1;
        }

        __syncthreads();   // all warps done reading Kf -> safe to alias with P
        uint32_t* Pp = reinterpret_cast<uint32_t*>(const_cast<float*>(Kf));
#pragma unroll
        for (int nf = 0; nf < 8; nf++) {
            *reinterpret_cast<uint2*>(&Pp[prow0 + nf * 8 + 2 * c]) =
                make_uint2(f2tf32(s[nf][0]), f2tf32(s[nf][1]));
            *reinterpret_cast<uint2*>(&Pp[prow1 + nf * 8 + 2 * c]) =
                make_uint2(f2tf32(s[nf][2]), f2tf32(s[nf][3]));
        }
        __syncwarp();      // P rows are warp-private

        // O += P V
#pragma unroll
        for (int ks = 0; ks < 8; ks++) {
            const int kk = ks * 8;
            uint32_t a[4];
            a[0] = Pp[prow0 + kk + c];
            a[1] = Pp[prow1 + kk + c];
            a[2] = Pp[prow0 + kk + c + 4];
            a[3] = Pp[prow1 + kk + c + 4];
#pragma unroll
            for (int nf = 0; nf < 8; nf++) {
                uint32_t b0 = f2tf32(Vf[(kk + c) * VSTRIDE + nf * 8 + g]);
                uint32_t b1 = f2tf32(Vf[(kk + c + 4) * VSTRIDE + nf * 8 + g]);
                mma_tf32(o[nf], a, b0, b1);
            }
        }
    }

    // epilogue
    float inv0 = 1.0f / l0, inv1 = 1.0f / l1;
    int row = qbase + w * 16 + g;
#pragma unroll
    for (int nf = 0; nf < 8; nf++) {
        int col = hoff + nf * 8 + 2 * c;
        *reinterpret_cast<float2*>(&O[row * HID + col]) =
            make_float2(o[nf][0] * inv0, o[nf][1] * inv0);
        *reinterpret_cast<float2*>(&O[(row + 8) * HID + col]) =
            make_float2(o[nf][2] * inv1, o[nf][3] * inv1);
    }
}

// ---------------------------------------------------------------------------
// Host launcher (graph-capturable: kernel launches only)
// Inputs: hidden, Wq, Wk, Wv, Wo, cos, sin, num_registers
// ---------------------------------------------------------------------------
extern "C" void kernel_launch(void* const* d_in, const int* in_sizes, int n_in,
                              void* d_out, int out_size) {
    const float* hs   = (const float*)d_in[0];
    const float* Wq   = (const float*)d_in[1];
    const float* Wk   = (const float*)d_in[2];
    const float* Wv   = (const float*)d_in[3];
    const float* Wo   = (const float*)d_in[4];
    const float* cosb = (const float*)d_in[5];
    const float* sinb = (const float*)d_in[6];
    const int*   nreg = (const int*)d_in[7];
    float* out = (float*)d_out;

    float *qp, *kp, *vp, *ap;
    cudaGetSymbolAddress((void**)&qp, g_q);
    cudaGetSymbolAddress((void**)&kp, g_k);
    cudaGetSymbolAddress((void**)&vp, g_v);
    cudaGetSymbolAddress((void**)&ap, g_att);

    cudaFuncSetAttribute(gemm_tf32, cudaFuncAttributeMaxDynamicSharedMemorySize, GEMM_SMEM);
    cudaFuncSetAttribute(attn_mma,  cudaFuncAttributeMaxDynamicSharedMemorySize, AT_SMEM);

    // fused QKV projections (gridDim.z selects weight/output)
    dim3 qkv_grid(GN / 64, S_LEN / 128, 3);
    gemm_tf32<<<qkv_grid, 256, GEMM_SMEM>>>(hs, Wq, Wk, Wv, qp, kp, vp);

    rope_kernel<<<(S_LEN * NHEAD * 32 + 255) / 256, 256>>>(qp, kp, cosb, sinb, nreg);

    attn_mma<<<512, 128, AT_SMEM>>>(qp, kp, vp, ap);

    dim3 o_grid(GN / 64, S_LEN / 128, 1);
    gemm_tf32<<<o_grid, 256, GEMM_SMEM>>>(ap, Wo, Wo, Wo, out, out, out);
}

// round 12
// speedup vs baseline: 2.0878x; 1.1152x over previous
#include <cuda_runtime.h>
#include <cstdint>

#define S_LEN 4096
#define HID   512
#define NHEAD 8
#define HDIM  64
#define GK    512
#define GN    512

// Scratch (device globals — allocation-free per harness rules)
// q/k/v/att hold tf32 bit-patterns (uint32) once the pipeline has run.
__device__ uint32_t g_q[S_LEN * HID];
__device__ uint32_t g_k[S_LEN * HID];
__device__ uint32_t g_v[S_LEN * HID];
__device__ uint32_t g_att[S_LEN * HID];
__device__ uint32_t g_hsu[S_LEN * HID];     // tf32(hidden_states)
__device__ uint32_t g_wqu[HID * HID];
__device__ uint32_t g_wku[HID * HID];
__device__ uint32_t g_wvu[HID * HID];
__device__ uint32_t g_wou[HID * HID];

// ---------------------------------------------------------------------------
// Helpers
// ---------------------------------------------------------------------------
__device__ __forceinline__ uint32_t f2tf32(float f) {
    uint32_t u;
    asm("cvt.rna.tf32.f32 %0, %1;" : "=r"(u) : "f"(f));
    return u;
}

__device__ __forceinline__ void mma_tf32(float c[4], const uint32_t a[4],
                                         uint32_t b0, uint32_t b1) {
    asm volatile(
        "mma.sync.aligned.m16n8k8.row.col.f32.tf32.tf32.f32 "
        "{%0,%1,%2,%3}, {%4,%5,%6,%7}, {%8,%9}, {%0,%1,%2,%3};"
        : "+f"(c[0]), "+f"(c[1]), "+f"(c[2]), "+f"(c[3])
        : "r"(a[0]), "r"(a[1]), "r"(a[2]), "r"(a[3]), "r"(b0), "r"(b1));
}

__device__ __forceinline__ uint32_t smem_u32(const void* p) {
    return (uint32_t)__cvta_generic_to_shared(p);
}

__device__ __forceinline__ void cp16(uint32_t dst, const void* src) {
    asm volatile("cp.async.cg.shared.global [%0], [%1], 16;" :: "r"(dst), "l"(src));
}
#define CP_COMMIT() asm volatile("cp.async.commit_group;")
#define CP_WAIT0()  asm volatile("cp.async.wait_group 0;")

// ---------------------------------------------------------------------------
// prep_cvt: one-shot tf32 conversion of hidden_states + 4 weight matrices.
// ---------------------------------------------------------------------------
#define HS4 ((S_LEN * HID) / 4)      // 524288
#define W4  ((HID * HID) / 4)        // 65536
#define PREP_TOTAL (HS4 + 4 * W4)    // 786432

__global__ void prep_cvt(const float* __restrict__ hs,
                         const float* __restrict__ wq,
                         const float* __restrict__ wk,
                         const float* __restrict__ wv,
                         const float* __restrict__ wo,
                         uint32_t* __restrict__ hsu,
                         uint32_t* __restrict__ wqu,
                         uint32_t* __restrict__ wku,
                         uint32_t* __restrict__ wvu,
                         uint32_t* __restrict__ wou) {
    int idx = blockIdx.x * blockDim.x + threadIdx.x;
    if (idx >= PREP_TOTAL) return;
    const float* src;
    uint32_t* dst;
    int off;
    if (idx < HS4) { src = hs; dst = hsu; off = idx; }
    else {
        int r = idx - HS4;
        int wsel = r / W4;
        off = r - wsel * W4;
        src = (wsel == 0) ? wq : (wsel == 1) ? wk : (wsel == 2) ? wv : wo;
        dst = (wsel == 0) ? wqu : (wsel == 1) ? wku : (wsel == 2) ? wvu : wou;
    }
    float4 v = *reinterpret_cast<const float4*>(src + off * 4);
    uint4 u = make_uint4(f2tf32(v.x), f2tf32(v.y), f2tf32(v.z), f2tf32(v.w));
    *reinterpret_cast<uint4*>(dst + off * 4) = u;
}

// ---------------------------------------------------------------------------
// C[4096,512] = A * B^T, tf32-bit operands (no cvt in mainloop), fp32 accum.
// CTA 128x64, BK=32, 256 thr, warp tile 32x32, cp.async double-buffered.
// Stride 36 (==4 mod 32): frag LDS conflict-free. Output: fp32, except
// blockIdx.z == cvt_z -> tf32 bits (used for V).
// ---------------------------------------------------------------------------
#define GA_BUF (128 * 36)
#define GB_BUF (64 * 36)
#define GEMM_SMEM ((2 * GA_BUF + 2 * GB_BUF) * 4)   // 55296 B

__global__ __launch_bounds__(256, 3) void gemm_u(const uint32_t* __restrict__ A,
                                                 const uint32_t* __restrict__ B0,
                                                 const uint32_t* __restrict__ B1,
                                                 const uint32_t* __restrict__ B2,
                                                 uint32_t* __restrict__ C0,
                                                 uint32_t* __restrict__ C1,
                                                 uint32_t* __restrict__ C2,
                                                 int cvt_z) {
    extern __shared__ uint32_t gsm[];
    uint32_t* Asm = gsm;                 // [2][128][36]
    uint32_t* Bsm = gsm + 2 * GA_BUF;    // [2][64][36]
    const uint32_t sA = smem_u32(Asm);
    const uint32_t sB = smem_u32(Bsm);

    const int z = blockIdx.z;
    const uint32_t* B = (z == 0) ? B0 : (z == 1) ? B1 : B2;
    uint32_t*       C = (z == 0) ? C0 : (z == 1) ? C1 : C2;
    const bool docvt = (z == cvt_z);

    const int tid = threadIdx.x;
    const int lane = tid & 31;
    const int warp = tid >> 5;
    const int g = lane >> 2;
    const int c = lane & 3;
    const int warp_m = warp & 3;
    const int warp_n = warp >> 2;
    const int mb = blockIdx.y * 128;
    const int nb = blockIdx.x * 64;

    auto stage = [&](int kb, int buf) {
        const int ab = buf * GA_BUF, bb = buf * GB_BUF;
#pragma unroll
        for (int i = 0; i < 4; i++) {
            int fid = tid + i * 256;
            int r = fid >> 3, c4 = fid & 7;
            cp16(sA + (ab + r * 36 + c4 * 4) * 4, A + (mb + r) * GK + kb + c4 * 4);
        }
#pragma unroll
        for (int i = 0; i < 2; i++) {
            int fid = tid + i * 256;
            int r = fid >> 3, c4 = fid & 7;
            cp16(sB + (bb + r * 36 + c4 * 4) * 4, B + (nb + r) * GK + kb + c4 * 4);
        }
        CP_COMMIT();
    };

    float acc[2][4][4];
#pragma unroll
    for (int mf = 0; mf < 2; mf++)
#pragma unroll
        for (int nf = 0; nf < 4; nf++)
#pragma unroll
            for (int r = 0; r < 4; r++) acc[mf][nf][r] = 0.f;

    stage(0, 0);

    for (int ib = 0; ib < GK / 32; ib++) {
        CP_WAIT0();
        __syncthreads();
        if (ib + 1 < GK / 32) stage((ib + 1) * 32, (ib + 1) & 1);

        const uint32_t* Ab = Asm + (ib & 1) * GA_BUF;
        const uint32_t* Bb = Bsm + (ib & 1) * GB_BUF;
#pragma unroll
        for (int ks = 0; ks < 4; ks++) {
            const int kk = ks * 8;
            uint32_t a[2][4];
#pragma unroll
            for (int mf = 0; mf < 2; mf++) {
                int rowb = warp_m * 32 + mf * 16 + g;
                a[mf][0] = Ab[rowb * 36 + kk + c];
                a[mf][1] = Ab[(rowb + 8) * 36 + kk + c];
                a[mf][2] = Ab[rowb * 36 + kk + c + 4];
                a[mf][3] = Ab[(rowb + 8) * 36 + kk + c + 4];
            }
            uint32_t b[4][2];
#pragma unroll
            for (int nf = 0; nf < 4; nf++) {
                int colb = warp_n * 32 + nf * 8 + g;
                b[nf][0] = Bb[colb * 36 + kk + c];
                b[nf][1] = Bb[colb * 36 + kk + c + 4];
            }
#pragma unroll
            for (int mf = 0; mf < 2; mf++)
#pragma unroll
                for (int nf = 0; nf < 4; nf++)
                    mma_tf32(acc[mf][nf], a[mf], b[nf][0], b[nf][1]);
        }
    }

#pragma unroll
    for (int mf = 0; mf < 2; mf++) {
        int row = mb + warp_m * 32 + mf * 16 + g;
#pragma unroll
        for (int nf = 0; nf < 4; nf++) {
            int col = nb + warp_n * 32 + nf * 8 + 2 * c;
            uint2 v0, v1;
            if (docvt) {
                v0 = make_uint2(f2tf32(acc[mf][nf][0]), f2tf32(acc[mf][nf][1]));
                v1 = make_uint2(f2tf32(acc[mf][nf][2]), f2tf32(acc[mf][nf][3]));
            } else {
                v0 = make_uint2(__float_as_uint(acc[mf][nf][0]), __float_as_uint(acc[mf][nf][1]));
                v1 = make_uint2(__float_as_uint(acc[mf][nf][2]), __float_as_uint(acc[mf][nf][3]));
            }
            *reinterpret_cast<uint2*>(&C[row * GN + col]) = v0;
            *reinterpret_cast<uint2*>(&C[(row + 8) * GN + col]) = v1;
        }
    }
}

// ---------------------------------------------------------------------------
// rope2: rotate q/k (fp32 in), write tf32 bits. Q is pre-scaled by 0.125
// (exact power of two -> commutes with tf32 rounding; bit-identical to the
// old frag-load path). Covers ALL positions (s < nreg: identity rotation).
// ---------------------------------------------------------------------------
__global__ void rope2_kernel(uint32_t* __restrict__ q, uint32_t* __restrict__ k,
                             const float* __restrict__ cosb,
                             const float* __restrict__ sinb,
                             const int* __restrict__ nregp) {
    const int nreg = *nregp;
    int idx = blockIdx.x * blockDim.x + threadIdx.x;
    if (idx >= S_LEN * NHEAD * 32) return;
    int j = idx & 31;
    int h = (idx >> 5) & 7;
    int s = idx >> 8;
    float c = 1.f, sn = 0.f;
    if (s >= nreg) {
        int p = s - nreg;
        c  = cosb[p * HDIM + j];
        sn = sinb[p * HDIM + j];
    }
    int base = s * HID + h * HDIM + j;
    float q1 = __uint_as_float(q[base]), q2 = __uint_as_float(q[base + 32]);
    q[base]      = f2tf32(0.125f * (q1 * c - q2 * sn));
    q[base + 32] = f2tf32(0.125f * (q2 * c + q1 * sn));
    float k1 = __uint_as_float(k[base]), k2 = __uint_as_float(k[base + 32]);
    k[base]      = f2tf32(k1 * c - k2 * sn);
    k[base + 32] = f2tf32(k2 * c + k1 * sn);
}

// ---------------------------------------------------------------------------
// Flash attention, causal, tf32 mma, cp.async double-buffered KV.
// All operands pre-converted tf32 bits -> zero cvt on Q/K/V paths.
// 64-query tile, 128 thr (4 warps x 16 rows), 3 CTAs/SM, no spills.
// K stride 68 (==4 mod 32), V stride 72 (==8 mod 32); P aliases the
// current K buffer after the S phase. Output written as tf32 bits.
// ---------------------------------------------------------------------------
#define KSTRIDE 68
#define VSTRIDE 72
#define KBUF (64 * KSTRIDE)          // 4352 words
#define VBUF (64 * VSTRIDE)          // 4608 words
#define AT_SMEM ((2 * KBUF + 2 * VBUF) * 4)   // 71680 B

__global__ __launch_bounds__(128, 3) void attn_mma(const uint32_t* __restrict__ Q,
                                                   const uint32_t* __restrict__ Kg,
                                                   const uint32_t* __restrict__ Vg,
                                                   uint32_t* __restrict__ O) {
    extern __shared__ uint32_t smu[];
    uint32_t* Ksm = smu;                  // [2][64][68]
    uint32_t* Vsm = smu + 2 * KBUF;       // [2][64][72]
    const uint32_t sK = smem_u32(Ksm);
    const uint32_t sV = smem_u32(Vsm);

    const int tid  = threadIdx.x;
    const int lane = tid & 31;
    const int w    = tid >> 5;
    const int g    = lane >> 2;
    const int c    = lane & 3;
    const int head = blockIdx.x & 7;
    const int qt   = 63 - (blockIdx.x >> 3);   // descending for LPT packing
    const int qbase = qt * 64;
    const int hoff  = head * HDIM;

    auto stage = [&](int t, int buf) {
        const int kb0 = t * 64;
        const int kb = buf * KBUF, vb = buf * VBUF;
#pragma unroll
        for (int i = 0; i < 8; i++) {
            int fid = tid + i * 128;
            int r = fid >> 4, c4 = fid & 15;
            cp16(sK + (kb + r * KSTRIDE + c4 * 4) * 4,
                 Kg + (kb0 + r) * HID + hoff + c4 * 4);
            cp16(sV + (vb + r * VSTRIDE + c4 * 4) * 4,
                 Vg + (kb0 + r) * HID + hoff + c4 * 4);
        }
        CP_COMMIT();
    };

    stage(0, 0);

    // Q fragments (already scaled + tf32)
    uint32_t qa[8][4];
    {
        const uint32_t* q0 = Q + (qbase + w * 16 + g) * HID + hoff;
        const uint32_t* q1 = q0 + 8 * HID;
#pragma unroll
        for (int ks = 0; ks < 8; ks++) {
            qa[ks][0] = __ldg(q0 + ks * 8 + c);
            qa[ks][1] = __ldg(q1 + ks * 8 + c);
            qa[ks][2] = __ldg(q0 + ks * 8 + c + 4);
            qa[ks][3] = __ldg(q1 + ks * 8 + c + 4);
        }
    }

    float o[8][4];
#pragma unroll
    for (int nf = 0; nf < 8; nf++)
#pragma unroll
        for (int r = 0; r < 4; r++) o[nf][r] = 0.f;
    float m0 = -1e30f, m1 = -1e30f, l0 = 0.f, l1 = 0.f;

    const int prow0 = (w * 16 + g) * KSTRIDE;
    const int prow1 = (w * 16 + g + 8) * KSTRIDE;

    for (int t = 0; t <= qt; t++) {
        CP_WAIT0();
        __syncthreads();   // tile t visible; all warps done with prior P/V reads
        if (t < qt) stage(t + 1, (t + 1) & 1);

        uint32_t* Kf = Ksm + (t & 1) * KBUF;
        const uint32_t* Vf = Vsm + (t & 1) * VBUF;

        // S = Q K^T
        float s[8][4];
#pragma unroll
        for (int nf = 0; nf < 8; nf++)
#pragma unroll
            for (int r = 0; r < 4; r++) s[nf][r] = 0.f;
#pragma unroll
        for (int ks = 0; ks < 8; ks++) {
            const int kk = ks * 8;
#pragma unroll
            for (int nf = 0; nf < 8; nf++) {
                uint32_t b0 = Kf[(nf * 8 + g) * KSTRIDE + kk + c];
                uint32_t b1 = Kf[(nf * 8 + g) * KSTRIDE + kk + c + 4];
                mma_tf32(s[nf], qa[ks], b0, b1);
            }
        }

        if (t == qt) {   // diagonal tile mask (local coords)
            int row0 = w * 16 + g, row1 = row0 + 8;
#pragma unroll
            for (int nf = 0; nf < 8; nf++) {
                int col = nf * 8 + 2 * c;
                if (col     > row0) s[nf][0] = -1e30f;
                if (col + 1 > row0) s[nf][1] = -1e30f;
                if (col     > row1) s[nf][2] = -1e30f;
                if (col + 1 > row1) s[nf][3] = -1e30f;
            }
        }

        // online softmax (rows r0: regs 0,1 / r1: regs 2,3)
        float mx0 = -1e30f, mx1 = -1e30f;
#pragma unroll
        for (int nf = 0; nf < 8; nf++) {
            mx0 = fmaxf(mx0, fmaxf(s[nf][0], s[nf][1]));
            mx1 = fmaxf(mx1, fmaxf(s[nf][2], s[nf][3]));
        }
        mx0 = fmaxf(mx0, __shfl_xor_sync(0xffffffffu, mx0, 1));
        mx0 = fmaxf(mx0, __shfl_xor_sync(0xffffffffu, mx0, 2));
        mx1 = fmaxf(mx1, __shfl_xor_sync(0xffffffffu, mx1, 1));
        mx1 = fmaxf(mx1, __shfl_xor_sync(0xffffffffu, mx1, 2));
        float mn0 = fmaxf(m0, mx0), mn1 = fmaxf(m1, mx1);
        float al0 = __expf(m0 - mn0), al1 = __expf(m1 - mn1);
        float sum0 = 0.f, sum1 = 0.f;
#pragma unroll
        for (int nf = 0; nf < 8; nf++) {
            s[nf][0] = __expf(s[nf][0] - mn0);
            s[nf][1] = __expf(s[nf][1] - mn0);
            sum0 += s[nf][0] + s[nf][1];
            s[nf][2] = __expf(s[nf][2] - mn1);
            s[nf][3] = __expf(s[nf][3] - mn1);
            sum1 += s[nf][2] + s[nf][3];
        }
        sum0 += __shfl_xor_sync(0xffffffffu, sum0, 1);
        sum0 += __shfl_xor_sync(0xffffffffu, sum0, 2);
        sum1 += __shfl_xor_sync(0xffffffffu, sum1, 1);
        sum1 += __shfl_xor_sync(0xffffffffu, sum1, 2);
        l0 = l0 * al0 + sum0;  m0 = mn0;
        l1 = l1 * al1 + sum1;  m1 = mn1;
#pragma unroll
        for (int nf = 0; nf < 8; nf++) {
            o[nf][0] *= al0;  o[nf][1] *= al0;
            o[nf][2] *= al1;  o[nf][3] *= al1;
        }

        __syncthreads();   // all warps done reading Kf -> safe to alias with P
        uint32_t* Pp = Kf;
#pragma unroll
        for (int nf = 0; nf < 8; nf++) {
            *reinterpret_cast<uint2*>(&Pp[prow0 + nf * 8 + 2 * c]) =
                make_uint2(f2tf32(s[nf][0]), f2tf32(s[nf][1]));
            *reinterpret_cast<uint2*>(&Pp[prow1 + nf * 8 + 2 * c]) =
                make_uint2(f2tf32(s[nf][2]), f2tf32(s[nf][3]));
        }
        __syncwarp();      // P rows are warp-private

        // O += P V
#pragma unroll
        for (int ks = 0; ks < 8; ks++) {
            const int kk = ks * 8;
            uint32_t a[4];
            a[0] = Pp[prow0 + kk + c];
            a[1] = Pp[prow1 + kk + c];
            a[2] = Pp[prow0 + kk + c + 4];
            a[3] = Pp[prow1 + kk + c + 4];
#pragma unroll
            for (int nf = 0; nf < 8; nf++) {
                uint32_t b0 = Vf[(kk + c) * VSTRIDE + nf * 8 + g];
                uint32_t b1 = Vf[(kk + c + 4) * VSTRIDE + nf * 8 + g];
                mma_tf32(o[nf], a, b0, b1);
            }
        }
    }

    // epilogue: write tf32 bits (O-projection consumes them directly)
    float inv0 = 1.0f / l0, inv1 = 1.0f / l1;
    int row = qbase + w * 16 + g;
#pragma unroll
    for (int nf = 0; nf < 8; nf++) {
        int col = hoff + nf * 8 + 2 * c;
        *reinterpret_cast<uint2*>(&O[row * HID + col]) =
            make_uint2(f2tf32(o[nf][0] * inv0), f2tf32(o[nf][1] * inv0));
        *reinterpret_cast<uint2*>(&O[(row + 8) * HID + col]) =
            make_uint2(f2tf32(o[nf][2] * inv1), f2tf32(o[nf][3] * inv1));
    }
}

// ---------------------------------------------------------------------------
// Host launcher (graph-capturable: kernel launches only)
// Inputs: hidden, Wq, Wk, Wv, Wo, cos, sin, num_registers
// ---------------------------------------------------------------------------
extern "C" void kernel_launch(void* const* d_in, const int* in_sizes, int n_in,
                              void* d_out, int out_size) {
    const float* hs   = (const float*)d_in[0];
    const float* Wq   = (const float*)d_in[1];
    const float* Wk   = (const float*)d_in[2];
    const float* Wv   = (const float*)d_in[3];
    const float* Wo   = (const float*)d_in[4];
    const float* cosb = (const float*)d_in[5];
    const float* sinb = (const float*)d_in[6];
    const int*   nreg = (const int*)d_in[7];
    uint32_t* out = (uint32_t*)d_out;

    uint32_t *qp, *kp, *vp, *ap, *hsu, *wqu, *wku, *wvu, *wou;
    cudaGetSymbolAddress((void**)&qp,  g_q);
    cudaGetSymbolAddress((void**)&kp,  g_k);
    cudaGetSymbolAddress((void**)&vp,  g_v);
    cudaGetSymbolAddress((void**)&ap,  g_att);
    cudaGetSymbolAddress((void**)&hsu, g_hsu);
    cudaGetSymbolAddress((void**)&wqu, g_wqu);
    cudaGetSymbolAddress((void**)&wku, g_wku);
    cudaGetSymbolAddress((void**)&wvu, g_wvu);
    cudaGetSymbolAddress((void**)&wou, g_wou);

    cudaFuncSetAttribute(gemm_u,   cudaFuncAttributeMaxDynamicSharedMemorySize, GEMM_SMEM);
    cudaFuncSetAttribute(attn_mma, cudaFuncAttributeMaxDynamicSharedMemorySize, AT_SMEM);

    // one-shot tf32 conversion of inputs
    prep_cvt<<<(PREP_TOTAL + 255) / 256, 256>>>(hs, Wq, Wk, Wv, Wo,
                                                hsu, wqu, wku, wvu, wou);

    // fused QKV projections; V (z==2) written directly as tf32 bits
    dim3 qkv_grid(GN / 64, S_LEN / 128, 3);
    gemm_u<<<qkv_grid, 256, GEMM_SMEM>>>(hsu, wqu, wku, wvu, qp, kp, vp, 2);

    // rope + scale + tf32 conversion of q/k (all positions)
    rope2_kernel<<<(S_LEN * NHEAD * 32 + 255) / 256, 256>>>(qp, kp, cosb, sinb, nreg);

    attn_mma<<<512, 128, AT_SMEM>>>(qp, kp, vp, ap);

    // O projection: fp32 output into d_out
    dim3 o_grid(GN / 64, S_LEN / 128, 1);
    gemm_u<<<o_grid, 256, GEMM_SMEM>>>(ap, wou, wou, wou, out, out, out, -1);
}